// round 1
// baseline (speedup 1.0000x reference)
#include <cuda_runtime.h>
#include <cuda_bf16.h>

// ---------------- problem constants ----------------
#define L_SEQ    2048
#define D_MODEL  1024
#define D_INNER  2048
#define D_XB     512
#define D_STATE  16
#define DT_RANK  64
#define KCONV    4
#define G_HEADS  128           // D_INNER / D_STATE
#define GX_HEADS 32            // D_XB / D_STATE
#define D_PROJ   5184          // 2*D_INNER + 2*D_XB + DT_RANK

// column offsets inside zxbcdt
#define OFF_Z    0
#define OFF_X    2048
#define OFF_B    2560
#define OFF_C    3072
#define OFF_DT   5120

// ---------------- scratch (static device globals; no allocation) ------------
__device__ float g_zx   [L_SEQ * D_PROJ];    // 42.5 MB
__device__ float g_delta[L_SEQ * D_INNER];   // 16.8 MB
__device__ float g_xconv[L_SEQ * D_XB];      //  4.2 MB
__device__ float g_yg   [L_SEQ * D_INNER];   // 16.8 MB

// ---------------- fp32 tiled SGEMM: C = A(MxK) @ B(KxN), row-major ----------
#define BM 128
#define BN 128
#define BK 8
#define TM 8
#define TN 8

__global__ __launch_bounds__(256)
void sgemm_kernel(const float* __restrict__ A, const float* __restrict__ B,
                  float* __restrict__ C, int M, int N, int K)
{
    __shared__ float As[BK][BM + 1];   // +1 pad: avoid STS bank conflicts on transpose
    __shared__ float Bs[BK][BN];

    const int tid  = threadIdx.x;
    const int brow = blockIdx.y;
    const int bcol = blockIdx.x;
    const int tr   = tid >> 4;         // 0..15
    const int tc   = tid & 15;         // 0..15
    const int colBase = bcol * BN;

    const float* Ab = A + (size_t)brow * BM * K;

    float acc[TM][TN];
    #pragma unroll
    for (int m = 0; m < TM; ++m)
        #pragma unroll
        for (int n = 0; n < TN; ++n) acc[m][n] = 0.f;

    for (int k0 = 0; k0 < K; k0 += BK) {
        // load A tile (BM x BK), store transposed.  M,K are multiples of 128/8 here.
        #pragma unroll
        for (int i = 0; i < 4; ++i) {
            int idx = tid + i * 256;
            int r = idx >> 3, c = idx & 7;
            As[c][r] = Ab[(size_t)r * K + k0 + c];
        }
        // load B tile (BK x BN) with column guard (N=5184 isn't a multiple of 128)
        #pragma unroll
        for (int i = 0; i < 4; ++i) {
            int idx = tid + i * 256;
            int r = idx >> 7, c = idx & 127;
            int col = colBase + c;
            Bs[r][c] = (col < N) ? B[(size_t)(k0 + r) * N + col] : 0.f;
        }
        __syncthreads();

        #pragma unroll
        for (int kk = 0; kk < BK; ++kk) {
            float ra[TM], rb[TN];
            #pragma unroll
            for (int m = 0; m < TM; ++m) ra[m] = As[kk][tr * TM + m];
            #pragma unroll
            for (int n = 0; n < TN; ++n) rb[n] = Bs[kk][tc * TN + n];
            #pragma unroll
            for (int m = 0; m < TM; ++m)
                #pragma unroll
                for (int n = 0; n < TN; ++n)
                    acc[m][n] = fmaf(ra[m], rb[n], acc[m][n]);
        }
        __syncthreads();
    }

    #pragma unroll
    for (int m = 0; m < TM; ++m) {
        int row = brow * BM + tr * TM + m;
        #pragma unroll
        for (int n = 0; n < TN; ++n) {
            int col = colBase + tc * TN + n;
            if (col < N) C[(size_t)row * N + col] = acc[m][n];
        }
    }
}

// ---------------- dt projection + softplus ----------------------------------
// delta[t,d] = softplus( dtr[t,:] @ W_dt[:,d] + 2*dt_bias[d] )
__global__ __launch_bounds__(256)
void dt_kernel(const float* __restrict__ W_dt, const float* __restrict__ dt_bias)
{
    const int t = blockIdx.x;
    __shared__ float r[DT_RANK];
    if (threadIdx.x < DT_RANK)
        r[threadIdx.x] = g_zx[(size_t)t * D_PROJ + OFF_DT + threadIdx.x];
    __syncthreads();

    for (int d = threadIdx.x; d < D_INNER; d += 256) {
        float s = 2.f * dt_bias[d];
        #pragma unroll 8
        for (int k = 0; k < DT_RANK; ++k)
            s = fmaf(r[k], W_dt[(size_t)k * D_INNER + d], s);
        // softplus (stable)
        float sp = (s > 20.f) ? s : log1pf(__expf(s));
        g_delta[(size_t)t * D_INNER + d] = sp;
    }
}

// ---------------- causal depthwise conv (K=4) + bias + silu -----------------
__global__ __launch_bounds__(256)
void conv_kernel(const float* __restrict__ w, const float* __restrict__ b)
{
    int idx = blockIdx.x * blockDim.x + threadIdx.x;   // t*512 + c
    if (idx >= L_SEQ * D_XB) return;
    int t = idx >> 9, c = idx & (D_XB - 1);
    float acc = b[c];
    #pragma unroll
    for (int k = 0; k < KCONV; ++k) {
        int tt = t - (KCONV - 1) + k;
        if (tt >= 0)
            acc = fmaf(w[c * KCONV + k], g_zx[(size_t)tt * D_PROJ + OFF_X + c], acc);
    }
    // silu
    g_xconv[idx] = acc / (1.f + __expf(-acc));
}

// ---------------- selective scan + output gating -----------------------------
// one block per head g; thread tid -> (p = tid/16, n = tid%16) state cell.
// h[t] = exp(delta*A)*h[t-1] + delta*x*B ;  y[t,g,p] = sum_n h*C
// yg[t,d] = (y + D[d]*x) * silu(z[t,d])
__global__ __launch_bounds__(256)
void scan_kernel(const float* __restrict__ A_log, const float* __restrict__ Dp)
{
    const int g   = blockIdx.x;           // 0..127
    const int tid = threadIdx.x;          // 0..255
    const int p   = tid >> 4;
    const int n   = tid & 15;
    const int gx  = g >> 2;               // repeat_kv: 4 consecutive g per gx
    const int d   = g * D_STATE + p;

    const float A  = -expf(A_log[d * D_STATE + n]);
    const float Dv = Dp[d];

    float h = 0.f;
    for (int t = 0; t < L_SEQ; ++t) {
        const float* row = g_zx + (size_t)t * D_PROJ;
        float dv = g_delta[(size_t)t * D_INNER + d];
        float xv = g_xconv[(size_t)t * D_XB + gx * D_STATE + p];
        float Bv = row[OFF_B + gx * D_STATE + n];
        float Cv = row[OFF_C + g * D_STATE + n];

        float a = __expf(dv * A);
        h = fmaf(a, h, dv * xv * Bv);

        float part = h * Cv;
        part += __shfl_xor_sync(0xffffffffu, part, 8);
        part += __shfl_xor_sync(0xffffffffu, part, 4);
        part += __shfl_xor_sync(0xffffffffu, part, 2);
        part += __shfl_xor_sync(0xffffffffu, part, 1);

        if (n == 0) {
            float zv = row[OFF_Z + d];
            float sz = zv / (1.f + __expf(-zv));
            g_yg[(size_t)t * D_INNER + d] = (part + Dv * xv) * sz;
        }
    }
}

// ---------------- launch ------------------------------------------------------
extern "C" void kernel_launch(void* const* d_in, const int* in_sizes, int n_in,
                              void* d_out, int out_size)
{
    const float* hidden  = (const float*)d_in[0];   // (1,2048,1024)
    const float* W_in    = (const float*)d_in[1];   // (1024,5184)
    const float* conv_w  = (const float*)d_in[2];   // (512,1,4)
    const float* conv_b  = (const float*)d_in[3];   // (512,)
    const float* W_dt    = (const float*)d_in[4];   // (64,2048)
    const float* dt_bias = (const float*)d_in[5];   // (2048,)
    const float* A_log   = (const float*)d_in[6];   // (2048,16)
    const float* Dp      = (const float*)d_in[7];   // (2048,)
    const float* W_out   = (const float*)d_in[8];   // (2048,1024)
    float*       out     = (float*)d_out;           // (1,2048,1024)

    float* zx    = nullptr;  cudaGetSymbolAddress((void**)&zx,    g_zx);
    float* yg    = nullptr;  cudaGetSymbolAddress((void**)&yg,    g_yg);

    // 1) zxbcdt = hidden @ W_in     (2048 x 1024 x 5184)
    {
        dim3 grid((D_PROJ + BN - 1) / BN, L_SEQ / BM);
        sgemm_kernel<<<grid, 256>>>(hidden, W_in, zx, L_SEQ, D_PROJ, D_MODEL);
    }
    // 2) delta = softplus(dtr @ W_dt + 2*dt_bias)
    dt_kernel<<<L_SEQ, 256>>>(W_dt, dt_bias);
    // 3) causal depthwise conv + silu on x
    conv_kernel<<<(L_SEQ * D_XB + 255) / 256, 256>>>(conv_w, conv_b);
    // 4) selective scan + gating -> yg
    scan_kernel<<<G_HEADS, 256>>>(A_log, Dp);
    // 5) out = yg @ W_out           (2048 x 2048 x 1024)
    {
        dim3 grid(D_MODEL / BN, L_SEQ / BM);
        sgemm_kernel<<<grid, 256>>>(yg, W_out, out, L_SEQ, D_MODEL, D_INNER);
    }
}

// round 3
// speedup vs baseline: 1.2648x; 1.2648x over previous
#include <cuda_runtime.h>
#include <cuda_bf16.h>
#include <cstdint>

// ---------------- problem constants ----------------
#define L_SEQ    2048
#define D_MODEL  1024
#define D_INNER  2048
#define D_XB     512
#define D_STATE  16
#define DT_RANK  64
#define KCONV    4
#define G_HEADS  128
#define GX_HEADS 32
#define D_PROJ   5184
#define NPAD1    5248          // D_PROJ padded to multiple of 128

#define OFF_Z    0
#define OFF_X    2048
#define OFF_B    2560
#define OFF_C    3072
#define OFF_DT   5120

// ---------------- scratch (static device globals; no runtime allocation) ----
__device__ float g_zx   [L_SEQ * D_PROJ];
__device__ float g_delta[L_SEQ * D_INNER];
__device__ float g_xconv[L_SEQ * D_XB];
__device__ float g_yg   [L_SEQ * D_INNER];

__device__ __nv_bfloat16 g_ahi [L_SEQ * D_INNER];       // max A: 2048x2048
__device__ __nv_bfloat16 g_alo [L_SEQ * D_INNER];
__device__ __nv_bfloat16 g_w1hi[NPAD1 * D_MODEL];       // W_in^T padded
__device__ __nv_bfloat16 g_w1lo[NPAD1 * D_MODEL];
__device__ __nv_bfloat16 g_w2hi[D_MODEL * D_INNER];     // W_out^T
__device__ __nv_bfloat16 g_w2lo[D_MODEL * D_INNER];

// ================= low-level helpers =========================================
__device__ __forceinline__ uint32_t smem_u32(const void* p) {
    return (uint32_t)__cvta_generic_to_shared(p);
}
__device__ __forceinline__ void cpasync16(uint32_t saddr, const void* g) {
    asm volatile("cp.async.cg.shared.global [%0], [%1], 16;" :: "r"(saddr), "l"(g));
}
__device__ __forceinline__ void ldsm4(uint32_t* r, uint32_t addr) {
    asm volatile("ldmatrix.sync.aligned.m8n8.x4.shared.b16 {%0,%1,%2,%3}, [%4];"
        : "=r"(r[0]), "=r"(r[1]), "=r"(r[2]), "=r"(r[3]) : "r"(addr));
}
__device__ __forceinline__ void mma16816(float* d, const uint32_t* a, const uint32_t* b) {
    asm volatile("mma.sync.aligned.m16n8k16.row.col.f32.bf16.bf16.f32 "
        "{%0,%1,%2,%3}, {%4,%5,%6,%7}, {%8,%9}, {%0,%1,%2,%3};"
        : "+f"(d[0]), "+f"(d[1]), "+f"(d[2]), "+f"(d[3])
        : "r"(a[0]), "r"(a[1]), "r"(a[2]), "r"(a[3]), "r"(b[0]), "r"(b[1]));
}
__device__ __forceinline__ uint32_t sw32(uint32_t off) {   // swizzle within 4KB tile
    return off ^ ((off >> 3) & 0x70);
}

// ================= fp32 -> bf16 hi/lo conversion =============================
__global__ void __launch_bounds__(256)
convert_hilo(const float* __restrict__ in, __nv_bfloat16* __restrict__ hi,
             __nv_bfloat16* __restrict__ lo, int count)
{
    int i = (blockIdx.x * 256 + threadIdx.x) * 4;
    if (i >= count) return;
    float4 v = *(const float4*)(in + i);
    float vv[4] = {v.x, v.y, v.z, v.w};
    __nv_bfloat16 h[4], l[4];
    #pragma unroll
    for (int j = 0; j < 4; ++j) {
        h[j] = __float2bfloat16_rn(vv[j]);
        l[j] = __float2bfloat16_rn(vv[j] - __bfloat162float(h[j]));
    }
    *(uint2*)(hi + i) = *(uint2*)h;
    *(uint2*)(lo + i) = *(uint2*)l;
}

// ================= transpose W [K,N] -> [Npad,K] bf16 hi/lo ==================
__global__ void __launch_bounds__(256)
transpose_wt(const float* __restrict__ W, __nv_bfloat16* __restrict__ Thi,
             __nv_bfloat16* __restrict__ Tlo, int K, int N)
{
    __shared__ float tile[32][33];
    int n0 = blockIdx.x * 32;
    int k0 = blockIdx.y * 32;
    int tx = threadIdx.x & 31, ty = threadIdx.x >> 5;    // 32 x 8
    #pragma unroll
    for (int r = 0; r < 4; ++r) {
        int k = k0 + ty + r * 8;
        int n = n0 + tx;
        tile[ty + r * 8][tx] = (n < N) ? W[(size_t)k * N + n] : 0.f;
    }
    __syncthreads();
    #pragma unroll
    for (int r = 0; r < 4; ++r) {
        int n = n0 + ty + r * 8;
        int k = k0 + tx;
        float v = tile[tx][ty + r * 8];
        __nv_bfloat16 h = __float2bfloat16_rn(v);
        Thi[(size_t)n * K + k] = h;
        Tlo[(size_t)n * K + k] = __float2bfloat16_rn(v - __bfloat162float(h));
    }
}

// ================= split-bf16 warp-MMA GEMM ==================================
// C[M, Nreal] = A[M,K] @ Bt[Npad,K]^T, fp32 accum via mma.sync m16n8k16.
// CTA tile 128x128, KTILE=16, 3-stage cp.async pipeline, 8 warps (2x4).
#define KTILE    16
#define STAGE_B  16384                    // 4 arrays x 4KB
#define GEMM_SMEM (3 * STAGE_B)           // 48KB: fits default dynamic limit

__global__ void __launch_bounds__(256)
gemm_tc_kernel(const __nv_bfloat16* __restrict__ Ahi, const __nv_bfloat16* __restrict__ Alo,
               const __nv_bfloat16* __restrict__ Bhi, const __nv_bfloat16* __restrict__ Blo,
               float* __restrict__ C, int Nreal, int K)
{
    extern __shared__ char sm[];
    const uint32_t sb = smem_u32(sm);
    const int tid   = threadIdx.x;
    const int lane  = tid & 31;
    const int wid   = tid >> 5;
    const int wm    = wid >> 2;            // 0..1
    const int wn    = wid & 3;             // 0..3
    const int nBase = blockIdx.x * 128;
    const int mBase = blockIdx.y * 128;
    const int wmB   = wm * 64;
    const int wnB   = wn * 32;

    const int nkt = K / KTILE;

    float acc[4][4][4];
    #pragma unroll
    for (int a = 0; a < 4; ++a)
        #pragma unroll
        for (int b = 0; b < 4; ++b)
            #pragma unroll
            for (int c = 0; c < 4; ++c) acc[a][b][c] = 0.f;

    // per-thread load assignment: 4 chunks of 16B per stage
    // idx in [0,1024): arr = idx>>8, within = idx&255, row = within>>1, ch = within&1
    int lrow[4], lch[4], larr[4];
    uint32_t lsw[4];
    #pragma unroll
    for (int i = 0; i < 4; ++i) {
        int idx = tid + i * 256;
        larr[i] = idx >> 8;
        int within = idx & 255;
        lrow[i] = within >> 1;
        lch[i]  = within & 1;
        lsw[i]  = sw32((uint32_t)lrow[i] * 32u + (uint32_t)lch[i] * 16u);
    }

    auto load_stage = [&](int stg, int kt) {
        const size_t koff = (size_t)kt * KTILE;
        uint32_t base = sb + (uint32_t)stg * STAGE_B;
        #pragma unroll
        for (int i = 0; i < 4; ++i) {
            const __nv_bfloat16* src;
            size_t goff;
            if (larr[i] < 2) {
                src = (larr[i] == 0) ? Ahi : Alo;
                goff = (size_t)(mBase + lrow[i]) * K + koff + (size_t)lch[i] * 8;
            } else {
                src = (larr[i] == 2) ? Bhi : Blo;
                goff = (size_t)(nBase + lrow[i]) * K + koff + (size_t)lch[i] * 8;
            }
            cpasync16(base + (uint32_t)larr[i] * 4096u + lsw[i], src + goff);
        }
        asm volatile("cp.async.commit_group;" ::: "memory");
    };

    // prologue: 2 stages in flight
    load_stage(0, 0);
    load_stage(1, 1);

    // ldmatrix per-lane offsets (within a 4KB array)
    // A: row = mf*16 + wmB + (lane&15); colbyte = (lane>>4)*16
    const uint32_t a_row = (uint32_t)(wmB + (lane & 15));
    const uint32_t a_cb  = (uint32_t)((lane >> 4) * 16);
    // B: row = wnB + nf2*16 + ((lane>>4)&1)*8 + (lane&7); colbyte = ((lane>>3)&1)*16
    const uint32_t b_row = (uint32_t)(wnB + ((lane >> 4) & 1) * 8 + (lane & 7));
    const uint32_t b_cb  = (uint32_t)(((lane >> 3) & 1) * 16);

    for (int kt = 0; kt < nkt; ++kt) {
        asm volatile("cp.async.wait_group 1;" ::: "memory");
        __syncthreads();

        const uint32_t stg = sb + (uint32_t)(kt % 3) * STAGE_B;
        const uint32_t sAhi = stg;
        const uint32_t sAlo = stg + 4096;
        const uint32_t sBhi = stg + 8192;
        const uint32_t sBlo = stg + 12288;

        // B fragments: 4 n-frags x 2 regs, hi and lo
        uint32_t bh[4][2], bl[4][2];
        #pragma unroll
        for (int nf2 = 0; nf2 < 2; ++nf2) {
            uint32_t off = sw32((b_row + (uint32_t)nf2 * 16u) * 32u + b_cb);
            uint32_t r[4];
            ldsm4(r, sBhi + off);
            bh[nf2*2][0] = r[0]; bh[nf2*2][1] = r[1];
            bh[nf2*2+1][0] = r[2]; bh[nf2*2+1][1] = r[3];
            ldsm4(r, sBlo + off);
            bl[nf2*2][0] = r[0]; bl[nf2*2][1] = r[1];
            bl[nf2*2+1][0] = r[2]; bl[nf2*2+1][1] = r[3];
        }

        #pragma unroll
        for (int mf = 0; mf < 4; ++mf) {
            uint32_t off = sw32((a_row + (uint32_t)mf * 16u) * 32u + a_cb);
            uint32_t ah[4], al[4];
            ldsm4(ah, sAhi + off);
            ldsm4(al, sAlo + off);
            #pragma unroll
            for (int nf = 0; nf < 4; ++nf) {
                mma16816(acc[mf][nf], ah, bh[nf]);
                mma16816(acc[mf][nf], ah, bl[nf]);
                mma16816(acc[mf][nf], al, bh[nf]);
            }
        }
        __syncthreads();
        if (kt + 2 < nkt) load_stage((kt + 2) % 3, kt + 2);
    }

    // epilogue
    const int gid = lane >> 2;
    const int tig = lane & 3;
    #pragma unroll
    for (int mf = 0; mf < 4; ++mf) {
        int row0 = mBase + wmB + mf * 16 + gid;
        #pragma unroll
        for (int nf = 0; nf < 4; ++nf) {
            int col = nBase + wnB + nf * 8 + tig * 2;
            if (col < Nreal) {
                float2 v0 = make_float2(acc[mf][nf][0], acc[mf][nf][1]);
                float2 v1 = make_float2(acc[mf][nf][2], acc[mf][nf][3]);
                *(float2*)(C + (size_t)row0 * Nreal + col) = v0;
                *(float2*)(C + (size_t)(row0 + 8) * Nreal + col) = v1;
            }
        }
    }
}

// ---------------- dt projection + softplus ----------------------------------
__global__ void __launch_bounds__(256)
dt_kernel(const float* __restrict__ W_dt, const float* __restrict__ dt_bias)
{
    const int t = blockIdx.x;
    __shared__ float r[DT_RANK];
    if (threadIdx.x < DT_RANK)
        r[threadIdx.x] = g_zx[(size_t)t * D_PROJ + OFF_DT + threadIdx.x];
    __syncthreads();

    for (int d = threadIdx.x; d < D_INNER; d += 256) {
        float s = 2.f * dt_bias[d];
        #pragma unroll 8
        for (int k = 0; k < DT_RANK; ++k)
            s = fmaf(r[k], W_dt[(size_t)k * D_INNER + d], s);
        float sp = (s > 20.f) ? s : log1pf(__expf(s));
        g_delta[(size_t)t * D_INNER + d] = sp;
    }
}

// ---------------- causal depthwise conv (K=4) + bias + silu -----------------
__global__ void __launch_bounds__(256)
conv_kernel(const float* __restrict__ w, const float* __restrict__ b)
{
    int idx = blockIdx.x * blockDim.x + threadIdx.x;
    if (idx >= L_SEQ * D_XB) return;
    int t = idx >> 9, c = idx & (D_XB - 1);
    float acc = b[c];
    #pragma unroll
    for (int k = 0; k < KCONV; ++k) {
        int tt = t - (KCONV - 1) + k;
        if (tt >= 0)
            acc = fmaf(w[c * KCONV + k], g_zx[(size_t)tt * D_PROJ + OFF_X + c], acc);
    }
    g_xconv[idx] = acc / (1.f + __expf(-acc));
}

// ---------------- selective scan + output gating -----------------------------
__global__ void __launch_bounds__(256)
scan_kernel(const float* __restrict__ A_log, const float* __restrict__ Dp)
{
    const int g   = blockIdx.x;
    const int tid = threadIdx.x;
    const int p   = tid >> 4;
    const int n   = tid & 15;
    const int gx  = g >> 2;
    const int d   = g * D_STATE + p;

    const float A  = -expf(A_log[d * D_STATE + n]);
    const float Dv = Dp[d];

    float h = 0.f;
    for (int t = 0; t < L_SEQ; ++t) {
        const float* row = g_zx + (size_t)t * D_PROJ;
        float dv = g_delta[(size_t)t * D_INNER + d];
        float xv = g_xconv[(size_t)t * D_XB + gx * D_STATE + p];
        float Bv = row[OFF_B + gx * D_STATE + n];
        float Cv = row[OFF_C + g * D_STATE + n];

        float a = __expf(dv * A);
        h = fmaf(a, h, dv * xv * Bv);

        float part = h * Cv;
        part += __shfl_xor_sync(0xffffffffu, part, 8);
        part += __shfl_xor_sync(0xffffffffu, part, 4);
        part += __shfl_xor_sync(0xffffffffu, part, 2);
        part += __shfl_xor_sync(0xffffffffu, part, 1);

        if (n == 0) {
            float zv = row[OFF_Z + d];
            float sz = zv / (1.f + __expf(-zv));
            g_yg[(size_t)t * D_INNER + d] = (part + Dv * xv) * sz;
        }
    }
}

// ---------------- launch ------------------------------------------------------
extern "C" void kernel_launch(void* const* d_in, const int* in_sizes, int n_in,
                              void* d_out, int out_size)
{
    const float* hidden  = (const float*)d_in[0];
    const float* W_in    = (const float*)d_in[1];
    const float* conv_w  = (const float*)d_in[2];
    const float* conv_b  = (const float*)d_in[3];
    const float* W_dt    = (const float*)d_in[4];
    const float* dt_bias = (const float*)d_in[5];
    const float* A_log   = (const float*)d_in[6];
    const float* Dp      = (const float*)d_in[7];
    const float* W_out   = (const float*)d_in[8];
    float*       out     = (float*)d_out;

    float *zx, *yg;
    __nv_bfloat16 *ahi, *alo, *w1hi, *w1lo, *w2hi, *w2lo;
    cudaGetSymbolAddress((void**)&zx,   g_zx);
    cudaGetSymbolAddress((void**)&yg,   g_yg);
    cudaGetSymbolAddress((void**)&ahi,  g_ahi);
    cudaGetSymbolAddress((void**)&alo,  g_alo);
    cudaGetSymbolAddress((void**)&w1hi, g_w1hi);
    cudaGetSymbolAddress((void**)&w1lo, g_w1lo);
    cudaGetSymbolAddress((void**)&w2hi, g_w2hi);
    cudaGetSymbolAddress((void**)&w2lo, g_w2lo);

    // 1) split/transpose operands for GEMM1
    convert_hilo<<<(L_SEQ * D_MODEL) / 1024, 256>>>(hidden, ahi, alo, L_SEQ * D_MODEL);
    transpose_wt<<<dim3(NPAD1 / 32, D_MODEL / 32), 256>>>(W_in, w1hi, w1lo, D_MODEL, D_PROJ);

    // 2) zxbcdt = hidden @ W_in   (2048 x 5184 x 1024)
    gemm_tc_kernel<<<dim3(NPAD1 / 128, L_SEQ / 128), 256, GEMM_SMEM>>>(
        ahi, alo, w1hi, w1lo, zx, D_PROJ, D_MODEL);

    // 3) delta, conv+silu, scan
    dt_kernel<<<L_SEQ, 256>>>(W_dt, dt_bias);
    conv_kernel<<<(L_SEQ * D_XB + 255) / 256, 256>>>(conv_w, conv_b);
    scan_kernel<<<G_HEADS, 256>>>(A_log, Dp);

    // 4) split/transpose operands for GEMM2
    convert_hilo<<<(L_SEQ * D_INNER) / 1024, 256>>>(yg, ahi, alo, L_SEQ * D_INNER);
    transpose_wt<<<dim3(D_MODEL / 32, D_INNER / 32), 256>>>(W_out, w2hi, w2lo, D_INNER, D_MODEL);

    // 5) out = yg @ W_out   (2048 x 1024 x 2048)
    gemm_tc_kernel<<<dim3(D_MODEL / 128, L_SEQ / 128), 256, GEMM_SMEM>>>(
        ahi, alo, w2hi, w2lo, out, D_MODEL, D_INNER);
}

// round 4
// speedup vs baseline: 5.5740x; 4.4070x over previous
#include <cuda_runtime.h>
#include <cuda_bf16.h>
#include <cstdint>

// ---------------- problem constants ----------------
#define L_SEQ    2048
#define D_MODEL  1024
#define D_INNER  2048
#define D_XB     512
#define D_STATE  16
#define DT_RANK  64
#define KCONV    4
#define G_HEADS  128
#define GX_HEADS 32
#define D_PROJ   5184
#define NPAD1    5248          // D_PROJ padded to multiple of 128

#define OFF_Z    0
#define OFF_X    2048
#define OFF_B    2560
#define OFF_C    3072
#define OFF_DT   5120

// scan chunking
#define CH       64
#define NCH      32            // L_SEQ / CH

// ---------------- scratch (static device globals; no runtime allocation) ----
__device__ float g_zx   [L_SEQ * D_PROJ];
__device__ float g_delta[L_SEQ * D_INNER];
__device__ float g_xconv[L_SEQ * D_XB];
__device__ float g_yg   [L_SEQ * D_INNER];

// chunked-scan intermediates: [NCH][G_HEADS][256]
__device__ float g_P  [NCH * G_HEADS * 256];
__device__ float g_E  [NCH * G_HEADS * 256];
__device__ float g_Cin[NCH * G_HEADS * 256];

__device__ __nv_bfloat16 g_ahi [L_SEQ * D_INNER];
__device__ __nv_bfloat16 g_alo [L_SEQ * D_INNER];
__device__ __nv_bfloat16 g_w1hi[NPAD1 * D_MODEL];
__device__ __nv_bfloat16 g_w1lo[NPAD1 * D_MODEL];
__device__ __nv_bfloat16 g_w2hi[D_MODEL * D_INNER];
__device__ __nv_bfloat16 g_w2lo[D_MODEL * D_INNER];

// ================= low-level helpers =========================================
__device__ __forceinline__ uint32_t smem_u32(const void* p) {
    return (uint32_t)__cvta_generic_to_shared(p);
}
__device__ __forceinline__ void cpasync16(uint32_t saddr, const void* g) {
    asm volatile("cp.async.cg.shared.global [%0], [%1], 16;" :: "r"(saddr), "l"(g));
}
__device__ __forceinline__ void ldsm4(uint32_t* r, uint32_t addr) {
    asm volatile("ldmatrix.sync.aligned.m8n8.x4.shared.b16 {%0,%1,%2,%3}, [%4];"
        : "=r"(r[0]), "=r"(r[1]), "=r"(r[2]), "=r"(r[3]) : "r"(addr));
}
__device__ __forceinline__ void mma16816(float* d, const uint32_t* a, const uint32_t* b) {
    asm volatile("mma.sync.aligned.m16n8k16.row.col.f32.bf16.bf16.f32 "
        "{%0,%1,%2,%3}, {%4,%5,%6,%7}, {%8,%9}, {%0,%1,%2,%3};"
        : "+f"(d[0]), "+f"(d[1]), "+f"(d[2]), "+f"(d[3])
        : "r"(a[0]), "r"(a[1]), "r"(a[2]), "r"(a[3]), "r"(b[0]), "r"(b[1]));
}
__device__ __forceinline__ uint32_t sw32(uint32_t off) {
    return off ^ ((off >> 3) & 0x70);
}

// ================= fp32 -> bf16 hi/lo conversion =============================
__global__ void __launch_bounds__(256)
convert_hilo(const float* __restrict__ in, __nv_bfloat16* __restrict__ hi,
             __nv_bfloat16* __restrict__ lo, int count)
{
    int i = (blockIdx.x * 256 + threadIdx.x) * 4;
    if (i >= count) return;
    float4 v = *(const float4*)(in + i);
    float vv[4] = {v.x, v.y, v.z, v.w};
    __nv_bfloat16 h[4], l[4];
    #pragma unroll
    for (int j = 0; j < 4; ++j) {
        h[j] = __float2bfloat16_rn(vv[j]);
        l[j] = __float2bfloat16_rn(vv[j] - __bfloat162float(h[j]));
    }
    *(uint2*)(hi + i) = *(uint2*)h;
    *(uint2*)(lo + i) = *(uint2*)l;
}

// ================= transpose W [K,N] -> [Npad,K] bf16 hi/lo ==================
__global__ void __launch_bounds__(256)
transpose_wt(const float* __restrict__ W, __nv_bfloat16* __restrict__ Thi,
             __nv_bfloat16* __restrict__ Tlo, int K, int N)
{
    __shared__ float tile[32][33];
    int n0 = blockIdx.x * 32;
    int k0 = blockIdx.y * 32;
    int tx = threadIdx.x & 31, ty = threadIdx.x >> 5;
    #pragma unroll
    for (int r = 0; r < 4; ++r) {
        int k = k0 + ty + r * 8;
        int n = n0 + tx;
        tile[ty + r * 8][tx] = (n < N) ? W[(size_t)k * N + n] : 0.f;
    }
    __syncthreads();
    #pragma unroll
    for (int r = 0; r < 4; ++r) {
        int n = n0 + ty + r * 8;
        int k = k0 + tx;
        float v = tile[tx][ty + r * 8];
        __nv_bfloat16 h = __float2bfloat16_rn(v);
        Thi[(size_t)n * K + k] = h;
        Tlo[(size_t)n * K + k] = __float2bfloat16_rn(v - __bfloat162float(h));
    }
}

// ================= split-bf16 warp-MMA GEMM (unchanged from R3) ==============
#define KTILE    16
#define STAGE_B  16384
#define GEMM_SMEM (3 * STAGE_B)

__global__ void __launch_bounds__(256)
gemm_tc_kernel(const __nv_bfloat16* __restrict__ Ahi, const __nv_bfloat16* __restrict__ Alo,
               const __nv_bfloat16* __restrict__ Bhi, const __nv_bfloat16* __restrict__ Blo,
               float* __restrict__ C, int Nreal, int K)
{
    extern __shared__ char sm[];
    const uint32_t sb = smem_u32(sm);
    const int tid   = threadIdx.x;
    const int lane  = tid & 31;
    const int wid   = tid >> 5;
    const int wm    = wid >> 2;
    const int wn    = wid & 3;
    const int nBase = blockIdx.x * 128;
    const int mBase = blockIdx.y * 128;
    const int wmB   = wm * 64;
    const int wnB   = wn * 32;

    const int nkt = K / KTILE;

    float acc[4][4][4];
    #pragma unroll
    for (int a = 0; a < 4; ++a)
        #pragma unroll
        for (int b = 0; b < 4; ++b)
            #pragma unroll
            for (int c = 0; c < 4; ++c) acc[a][b][c] = 0.f;

    int lrow[4], lch[4], larr[4];
    uint32_t lsw[4];
    #pragma unroll
    for (int i = 0; i < 4; ++i) {
        int idx = tid + i * 256;
        larr[i] = idx >> 8;
        int within = idx & 255;
        lrow[i] = within >> 1;
        lch[i]  = within & 1;
        lsw[i]  = sw32((uint32_t)lrow[i] * 32u + (uint32_t)lch[i] * 16u);
    }

    auto load_stage = [&](int stg, int kt) {
        const size_t koff = (size_t)kt * KTILE;
        uint32_t base = sb + (uint32_t)stg * STAGE_B;
        #pragma unroll
        for (int i = 0; i < 4; ++i) {
            const __nv_bfloat16* src;
            size_t goff;
            if (larr[i] < 2) {
                src = (larr[i] == 0) ? Ahi : Alo;
                goff = (size_t)(mBase + lrow[i]) * K + koff + (size_t)lch[i] * 8;
            } else {
                src = (larr[i] == 2) ? Bhi : Blo;
                goff = (size_t)(nBase + lrow[i]) * K + koff + (size_t)lch[i] * 8;
            }
            cpasync16(base + (uint32_t)larr[i] * 4096u + lsw[i], src + goff);
        }
        asm volatile("cp.async.commit_group;" ::: "memory");
    };

    load_stage(0, 0);
    load_stage(1, 1);

    const uint32_t a_row = (uint32_t)(wmB + (lane & 15));
    const uint32_t a_cb  = (uint32_t)((lane >> 4) * 16);
    const uint32_t b_row = (uint32_t)(wnB + ((lane >> 4) & 1) * 8 + (lane & 7));
    const uint32_t b_cb  = (uint32_t)(((lane >> 3) & 1) * 16);

    for (int kt = 0; kt < nkt; ++kt) {
        asm volatile("cp.async.wait_group 1;" ::: "memory");
        __syncthreads();

        const uint32_t stg = sb + (uint32_t)(kt % 3) * STAGE_B;
        const uint32_t sAhi = stg;
        const uint32_t sAlo = stg + 4096;
        const uint32_t sBhi = stg + 8192;
        const uint32_t sBlo = stg + 12288;

        uint32_t bh[4][2], bl[4][2];
        #pragma unroll
        for (int nf2 = 0; nf2 < 2; ++nf2) {
            uint32_t off = sw32((b_row + (uint32_t)nf2 * 16u) * 32u + b_cb);
            uint32_t r[4];
            ldsm4(r, sBhi + off);
            bh[nf2*2][0] = r[0]; bh[nf2*2][1] = r[1];
            bh[nf2*2+1][0] = r[2]; bh[nf2*2+1][1] = r[3];
            ldsm4(r, sBlo + off);
            bl[nf2*2][0] = r[0]; bl[nf2*2][1] = r[1];
            bl[nf2*2+1][0] = r[2]; bl[nf2*2+1][1] = r[3];
        }

        #pragma unroll
        for (int mf = 0; mf < 4; ++mf) {
            uint32_t off = sw32((a_row + (uint32_t)mf * 16u) * 32u + a_cb);
            uint32_t ah[4], al[4];
            ldsm4(ah, sAhi + off);
            ldsm4(al, sAlo + off);
            #pragma unroll
            for (int nf = 0; nf < 4; ++nf) {
                mma16816(acc[mf][nf], ah, bh[nf]);
                mma16816(acc[mf][nf], ah, bl[nf]);
                mma16816(acc[mf][nf], al, bh[nf]);
            }
        }
        __syncthreads();
        if (kt + 2 < nkt) load_stage((kt + 2) % 3, kt + 2);
    }

    const int gid = lane >> 2;
    const int tig = lane & 3;
    #pragma unroll
    for (int mf = 0; mf < 4; ++mf) {
        int row0 = mBase + wmB + mf * 16 + gid;
        #pragma unroll
        for (int nf = 0; nf < 4; ++nf) {
            int col = nBase + wnB + nf * 8 + tig * 2;
            if (col < Nreal) {
                float2 v0 = make_float2(acc[mf][nf][0], acc[mf][nf][1]);
                float2 v1 = make_float2(acc[mf][nf][2], acc[mf][nf][3]);
                *(float2*)(C + (size_t)row0 * Nreal + col) = v0;
                *(float2*)(C + (size_t)(row0 + 8) * Nreal + col) = v1;
            }
        }
    }
}

// ---------------- dt projection + softplus (tiled, W_dt read 16x not 2048x) --
// grid: (L_SEQ/128, D_INNER/256); block 256: thread owns one d column.
__global__ void __launch_bounds__(256)
dt_kernel(const float* __restrict__ W_dt, const float* __restrict__ dt_bias)
{
    __shared__ float s_r[128 * DT_RANK];   // 32KB: dtr tile
    const int t0 = blockIdx.x * 128;
    const int d  = blockIdx.y * 256 + threadIdx.x;

    // coalesced load of dtr tile: 8192 elems / 256 threads = 32 each
    #pragma unroll
    for (int k = 0; k < 32; ++k) {
        int idx = threadIdx.x + k * 256;
        int row = idx >> 6, col = idx & 63;
        s_r[idx] = g_zx[(size_t)(t0 + row) * D_PROJ + OFF_DT + col];
    }
    __syncthreads();

    // W_dt column into registers (coalesced across threads)
    float w[DT_RANK];
    #pragma unroll
    for (int k = 0; k < DT_RANK; ++k)
        w[k] = W_dt[(size_t)k * D_INNER + d];

    const float bias2 = 2.f * dt_bias[d];

    for (int tt = 0; tt < 128; ++tt) {
        const float4* rp = (const float4*)(s_r + tt * DT_RANK);
        float s = bias2;
        #pragma unroll
        for (int k4 = 0; k4 < DT_RANK / 4; ++k4) {
            float4 r4 = rp[k4];
            s = fmaf(r4.x, w[k4*4+0], s);
            s = fmaf(r4.y, w[k4*4+1], s);
            s = fmaf(r4.z, w[k4*4+2], s);
            s = fmaf(r4.w, w[k4*4+3], s);
        }
        float sp = (s > 20.f) ? s : log1pf(__expf(s));
        g_delta[(size_t)(t0 + tt) * D_INNER + d] = sp;
    }
}

// ---------------- causal depthwise conv (K=4) + bias + silu -----------------
__global__ void __launch_bounds__(256)
conv_kernel(const float* __restrict__ w, const float* __restrict__ b)
{
    int idx = blockIdx.x * blockDim.x + threadIdx.x;
    if (idx >= L_SEQ * D_XB) return;
    int t = idx >> 9, c = idx & (D_XB - 1);
    float acc = b[c];
    #pragma unroll
    for (int k = 0; k < KCONV; ++k) {
        int tt = t - (KCONV - 1) + k;
        if (tt >= 0)
            acc = fmaf(w[c * KCONV + k], g_zx[(size_t)tt * D_PROJ + OFF_X + c], acc);
    }
    g_xconv[idx] = acc / (1.f + __expf(-acc));
}

// ---------------- chunked selective scan -------------------------------------
// Phase A: per-chunk local scan from h=0 -> (P = prod a, E = h_end)
__global__ void __launch_bounds__(256)
scan_phase_a(const float* __restrict__ A_log)
{
    const int g   = blockIdx.x;           // 0..127
    const int j   = blockIdx.y;           // 0..NCH-1
    const int tid = threadIdx.x;
    const int p   = tid >> 4;
    const int n   = tid & 15;
    const int gx  = g >> 2;
    const int d   = g * D_STATE + p;

    __shared__ float s_dv[CH * 16], s_xv[CH * 16], s_B[CH * 16];

    const int i0 = tid >> 4, l = tid & 15;
    const int tbase = j * CH;
    #pragma unroll
    for (int r = 0; r < CH; r += 16) {
        int t = tbase + i0 + r;
        s_dv[(i0 + r) * 16 + l] = g_delta[(size_t)t * D_INNER + g * 16 + l];
        s_xv[(i0 + r) * 16 + l] = g_xconv[(size_t)t * D_XB + gx * 16 + l];
        s_B [(i0 + r) * 16 + l] = g_zx[(size_t)t * D_PROJ + OFF_B + gx * 16 + l];
    }
    __syncthreads();

    const float A = -expf(A_log[d * D_STATE + n]);
    float h = 0.f, P = 1.f;
    #pragma unroll 8
    for (int i = 0; i < CH; ++i) {
        float dv = s_dv[i * 16 + p];
        float xv = s_xv[i * 16 + p];
        float Bv = s_B [i * 16 + n];
        float a  = __expf(dv * A);
        P *= a;
        h = fmaf(a, h, dv * xv * Bv);
    }
    int idx = (j * G_HEADS + g) * 256 + tid;
    g_P[idx] = P;
    g_E[idx] = h;
}

// Phase B: sequential combine over chunks -> carry-in per chunk
__global__ void __launch_bounds__(256)
scan_phase_b()
{
    const int g   = blockIdx.x;
    const int tid = threadIdx.x;
    float c = 0.f;
    #pragma unroll
    for (int j = 0; j < NCH; ++j) {
        int idx = (j * G_HEADS + g) * 256 + tid;
        float P = g_P[idx];
        float E = g_E[idx];
        g_Cin[idx] = c;
        c = fmaf(P, c, E);
    }
}

// Phase C: replay chunk with carry, reduce over n with C, gate, store yg
__global__ void __launch_bounds__(256)
scan_phase_c(const float* __restrict__ A_log, const float* __restrict__ Dp)
{
    const int g   = blockIdx.x;
    const int j   = blockIdx.y;
    const int tid = threadIdx.x;
    const int p   = tid >> 4;
    const int n   = tid & 15;
    const int gx  = g >> 2;
    const int d   = g * D_STATE + p;

    __shared__ float s_dv[CH * 16], s_xv[CH * 16], s_B[CH * 16],
                     s_C [CH * 16], s_z [CH * 16];

    const int i0 = tid >> 4, l = tid & 15;
    const int tbase = j * CH;
    #pragma unroll
    for (int r = 0; r < CH; r += 16) {
        int t = tbase + i0 + r;
        s_dv[(i0 + r) * 16 + l] = g_delta[(size_t)t * D_INNER + g * 16 + l];
        s_xv[(i0 + r) * 16 + l] = g_xconv[(size_t)t * D_XB + gx * 16 + l];
        s_B [(i0 + r) * 16 + l] = g_zx[(size_t)t * D_PROJ + OFF_B + gx * 16 + l];
        s_C [(i0 + r) * 16 + l] = g_zx[(size_t)t * D_PROJ + OFF_C + g * 16 + l];
        s_z [(i0 + r) * 16 + l] = g_zx[(size_t)t * D_PROJ + OFF_Z + g * 16 + l];
    }
    __syncthreads();

    const float A  = -expf(A_log[d * D_STATE + n]);
    const float Dv = Dp[d];
    float h = g_Cin[(j * G_HEADS + g) * 256 + tid];

    #pragma unroll 4
    for (int i = 0; i < CH; ++i) {
        float dv = s_dv[i * 16 + p];
        float xv = s_xv[i * 16 + p];
        float Bv = s_B [i * 16 + n];
        float Cv = s_C [i * 16 + n];

        float a = __expf(dv * A);
        h = fmaf(a, h, dv * xv * Bv);

        float part = h * Cv;
        part += __shfl_xor_sync(0xffffffffu, part, 8);
        part += __shfl_xor_sync(0xffffffffu, part, 4);
        part += __shfl_xor_sync(0xffffffffu, part, 2);
        part += __shfl_xor_sync(0xffffffffu, part, 1);

        if (n == 0) {
            float zv = s_z[i * 16 + p];
            float sz = zv / (1.f + __expf(-zv));
            g_yg[(size_t)(tbase + i) * D_INNER + d] = (part + Dv * xv) * sz;
        }
    }
}

// ---------------- launch ------------------------------------------------------
extern "C" void kernel_launch(void* const* d_in, const int* in_sizes, int n_in,
                              void* d_out, int out_size)
{
    const float* hidden  = (const float*)d_in[0];
    const float* W_in    = (const float*)d_in[1];
    const float* conv_w  = (const float*)d_in[2];
    const float* conv_b  = (const float*)d_in[3];
    const float* W_dt    = (const float*)d_in[4];
    const float* dt_bias = (const float*)d_in[5];
    const float* A_log   = (const float*)d_in[6];
    const float* Dp      = (const float*)d_in[7];
    const float* W_out   = (const float*)d_in[8];
    float*       out     = (float*)d_out;

    float *zx, *yg;
    __nv_bfloat16 *ahi, *alo, *w1hi, *w1lo, *w2hi, *w2lo;
    cudaGetSymbolAddress((void**)&zx,   g_zx);
    cudaGetSymbolAddress((void**)&yg,   g_yg);
    cudaGetSymbolAddress((void**)&ahi,  g_ahi);
    cudaGetSymbolAddress((void**)&alo,  g_alo);
    cudaGetSymbolAddress((void**)&w1hi, g_w1hi);
    cudaGetSymbolAddress((void**)&w1lo, g_w1lo);
    cudaGetSymbolAddress((void**)&w2hi, g_w2hi);
    cudaGetSymbolAddress((void**)&w2lo, g_w2lo);

    // 1) split/transpose operands for GEMM1
    convert_hilo<<<(L_SEQ * D_MODEL) / 1024, 256>>>(hidden, ahi, alo, L_SEQ * D_MODEL);
    transpose_wt<<<dim3(NPAD1 / 32, D_MODEL / 32), 256>>>(W_in, w1hi, w1lo, D_MODEL, D_PROJ);

    // 2) zxbcdt = hidden @ W_in
    gemm_tc_kernel<<<dim3(NPAD1 / 128, L_SEQ / 128), 256, GEMM_SMEM>>>(
        ahi, alo, w1hi, w1lo, zx, D_PROJ, D_MODEL);

    // 3) delta + conv
    dt_kernel<<<dim3(L_SEQ / 128, D_INNER / 256), 256>>>(W_dt, dt_bias);
    conv_kernel<<<(L_SEQ * D_XB + 255) / 256, 256>>>(conv_w, conv_b);

    // 4) chunked scan
    scan_phase_a<<<dim3(G_HEADS, NCH), 256>>>(A_log);
    scan_phase_b<<<G_HEADS, 256>>>();
    scan_phase_c<<<dim3(G_HEADS, NCH), 256>>>(A_log, Dp);

    // 5) split/transpose operands for GEMM2
    convert_hilo<<<(L_SEQ * D_INNER) / 1024, 256>>>(yg, ahi, alo, L_SEQ * D_INNER);
    transpose_wt<<<dim3(D_MODEL / 32, D_INNER / 32), 256>>>(W_out, w2hi, w2lo, D_INNER, D_MODEL);

    // 6) out = yg @ W_out
    gemm_tc_kernel<<<dim3(D_MODEL / 128, L_SEQ / 128), 256, GEMM_SMEM>>>(
        ahi, alo, w2hi, w2lo, out, D_MODEL, D_INNER);
}

// round 5
// speedup vs baseline: 6.2668x; 1.1243x over previous
#include <cuda_runtime.h>
#include <cuda_bf16.h>
#include <cstdint>

// ---------------- problem constants ----------------
#define L_SEQ    2048
#define D_MODEL  1024
#define D_INNER  2048
#define D_XB     512
#define D_STATE  16
#define DT_RANK  64
#define KCONV    4
#define G_HEADS  128
#define GX_HEADS 32
#define D_PROJ   5184
#define NPAD1    5248          // D_PROJ padded to multiple of 128

#define OFF_Z    0
#define OFF_X    2048
#define OFF_B    2560
#define OFF_C    3072
#define OFF_DT   5120

// scan chunking
#define CH       64
#define NCH      32            // L_SEQ / CH

// ---------------- scratch (static device globals; no runtime allocation) ----
__device__ float g_zx   [L_SEQ * D_PROJ];
__device__ float g_delta[L_SEQ * D_INNER];
__device__ float g_xconv[L_SEQ * D_XB];

// chunked-scan intermediates: [NCH][G_HEADS][256]
__device__ float g_P  [NCH * G_HEADS * 256];
__device__ float g_E  [NCH * G_HEADS * 256];
__device__ float g_Cin[NCH * G_HEADS * 256];

__device__ __nv_bfloat16 g_ahi [L_SEQ * D_INNER];
__device__ __nv_bfloat16 g_alo [L_SEQ * D_INNER];
__device__ __nv_bfloat16 g_w1hi[NPAD1 * D_MODEL];
__device__ __nv_bfloat16 g_w1lo[NPAD1 * D_MODEL];
__device__ __nv_bfloat16 g_w2hi[D_MODEL * D_INNER];
__device__ __nv_bfloat16 g_w2lo[D_MODEL * D_INNER];

// ================= low-level helpers =========================================
__device__ __forceinline__ uint32_t smem_u32(const void* p) {
    return (uint32_t)__cvta_generic_to_shared(p);
}
__device__ __forceinline__ void cpasync16(uint32_t saddr, const void* g) {
    asm volatile("cp.async.cg.shared.global [%0], [%1], 16;" :: "r"(saddr), "l"(g));
}
__device__ __forceinline__ void ldsm4(uint32_t* r, uint32_t addr) {
    asm volatile("ldmatrix.sync.aligned.m8n8.x4.shared.b16 {%0,%1,%2,%3}, [%4];"
        : "=r"(r[0]), "=r"(r[1]), "=r"(r[2]), "=r"(r[3]) : "r"(addr));
}
__device__ __forceinline__ void mma16816(float* d, const uint32_t* a, const uint32_t* b) {
    asm volatile("mma.sync.aligned.m16n8k16.row.col.f32.bf16.bf16.f32 "
        "{%0,%1,%2,%3}, {%4,%5,%6,%7}, {%8,%9}, {%0,%1,%2,%3};"
        : "+f"(d[0]), "+f"(d[1]), "+f"(d[2]), "+f"(d[3])
        : "r"(a[0]), "r"(a[1]), "r"(a[2]), "r"(a[3]), "r"(b[0]), "r"(b[1]));
}
__device__ __forceinline__ uint32_t sw32(uint32_t off) {
    return off ^ ((off >> 3) & 0x70);
}

// ================= fp32 -> bf16 hi/lo conversion =============================
__global__ void __launch_bounds__(256)
convert_hilo(const float* __restrict__ in, __nv_bfloat16* __restrict__ hi,
             __nv_bfloat16* __restrict__ lo, int count)
{
    int i = (blockIdx.x * 256 + threadIdx.x) * 4;
    if (i >= count) return;
    float4 v = *(const float4*)(in + i);
    float vv[4] = {v.x, v.y, v.z, v.w};
    __nv_bfloat16 h[4], l[4];
    #pragma unroll
    for (int j = 0; j < 4; ++j) {
        h[j] = __float2bfloat16_rn(vv[j]);
        l[j] = __float2bfloat16_rn(vv[j] - __bfloat162float(h[j]));
    }
    *(uint2*)(hi + i) = *(uint2*)h;
    *(uint2*)(lo + i) = *(uint2*)l;
}

// ================= transpose W [K,N] -> [Npad,K] bf16 hi/lo ==================
__global__ void __launch_bounds__(256)
transpose_wt(const float* __restrict__ W, __nv_bfloat16* __restrict__ Thi,
             __nv_bfloat16* __restrict__ Tlo, int K, int N)
{
    __shared__ float tile[32][33];
    int n0 = blockIdx.x * 32;
    int k0 = blockIdx.y * 32;
    int tx = threadIdx.x & 31, ty = threadIdx.x >> 5;
    #pragma unroll
    for (int r = 0; r < 4; ++r) {
        int k = k0 + ty + r * 8;
        int n = n0 + tx;
        tile[ty + r * 8][tx] = (n < N) ? W[(size_t)k * N + n] : 0.f;
    }
    __syncthreads();
    #pragma unroll
    for (int r = 0; r < 4; ++r) {
        int n = n0 + ty + r * 8;
        int k = k0 + tx;
        float v = tile[tx][ty + r * 8];
        __nv_bfloat16 h = __float2bfloat16_rn(v);
        Thi[(size_t)n * K + k] = h;
        Tlo[(size_t)n * K + k] = __float2bfloat16_rn(v - __bfloat162float(h));
    }
}

// ================= split-bf16 warp-MMA GEMM ==================================
// CTA tile 128x128, KTILE=16, 4-stage cp.async pipeline, 8 warps, 2 CTAs/SM.
#define KTILE    16
#define STAGE_B  16384
#define NSTAGE   4
#define GEMM_SMEM (NSTAGE * STAGE_B)      // 64KB (needs attribute)

__global__ void __launch_bounds__(256, 2)
gemm_tc_kernel(const __nv_bfloat16* __restrict__ Ahi, const __nv_bfloat16* __restrict__ Alo,
               const __nv_bfloat16* __restrict__ Bhi, const __nv_bfloat16* __restrict__ Blo,
               float* __restrict__ C, int Nreal, int K)
{
    extern __shared__ char sm[];
    const uint32_t sb = smem_u32(sm);
    const int tid   = threadIdx.x;
    const int lane  = tid & 31;
    const int wid   = tid >> 5;
    const int wm    = wid >> 2;
    const int wn    = wid & 3;
    const int nBase = blockIdx.x * 128;
    const int mBase = blockIdx.y * 128;
    const int wmB   = wm * 64;
    const int wnB   = wn * 32;

    const int nkt = K / KTILE;

    float acc[4][4][4];
    #pragma unroll
    for (int a = 0; a < 4; ++a)
        #pragma unroll
        for (int b = 0; b < 4; ++b)
            #pragma unroll
            for (int c = 0; c < 4; ++c) acc[a][b][c] = 0.f;

    int lrow[4], lch[4], larr[4];
    uint32_t lsw[4];
    #pragma unroll
    for (int i = 0; i < 4; ++i) {
        int idx = tid + i * 256;
        larr[i] = idx >> 8;
        int within = idx & 255;
        lrow[i] = within >> 1;
        lch[i]  = within & 1;
        lsw[i]  = sw32((uint32_t)lrow[i] * 32u + (uint32_t)lch[i] * 16u);
    }

    auto load_stage = [&](int stg, int kt) {
        const size_t koff = (size_t)kt * KTILE;
        uint32_t base = sb + (uint32_t)stg * STAGE_B;
        #pragma unroll
        for (int i = 0; i < 4; ++i) {
            const __nv_bfloat16* src;
            size_t goff;
            if (larr[i] < 2) {
                src = (larr[i] == 0) ? Ahi : Alo;
                goff = (size_t)(mBase + lrow[i]) * K + koff + (size_t)lch[i] * 8;
            } else {
                src = (larr[i] == 2) ? Bhi : Blo;
                goff = (size_t)(nBase + lrow[i]) * K + koff + (size_t)lch[i] * 8;
            }
            cpasync16(base + (uint32_t)larr[i] * 4096u + lsw[i], src + goff);
        }
        asm volatile("cp.async.commit_group;" ::: "memory");
    };

    // prologue: 3 stages in flight
    load_stage(0, 0);
    load_stage(1, 1);
    load_stage(2, 2);

    const uint32_t a_row = (uint32_t)(wmB + (lane & 15));
    const uint32_t a_cb  = (uint32_t)((lane >> 4) * 16);
    const uint32_t b_row = (uint32_t)(wnB + ((lane >> 4) & 1) * 8 + (lane & 7));
    const uint32_t b_cb  = (uint32_t)(((lane >> 3) & 1) * 16);

    for (int kt = 0; kt < nkt; ++kt) {
        asm volatile("cp.async.wait_group 2;" ::: "memory");
        __syncthreads();   // also guarantees stage (kt-1)%4 fully consumed by all warps

        const uint32_t stg = sb + (uint32_t)(kt % NSTAGE) * STAGE_B;
        const uint32_t sAhi = stg;
        const uint32_t sAlo = stg + 4096;
        const uint32_t sBhi = stg + 8192;
        const uint32_t sBlo = stg + 12288;

        uint32_t bh[4][2], bl[4][2];
        #pragma unroll
        for (int nf2 = 0; nf2 < 2; ++nf2) {
            uint32_t off = sw32((b_row + (uint32_t)nf2 * 16u) * 32u + b_cb);
            uint32_t r[4];
            ldsm4(r, sBhi + off);
            bh[nf2*2][0] = r[0]; bh[nf2*2][1] = r[1];
            bh[nf2*2+1][0] = r[2]; bh[nf2*2+1][1] = r[3];
            ldsm4(r, sBlo + off);
            bl[nf2*2][0] = r[0]; bl[nf2*2][1] = r[1];
            bl[nf2*2+1][0] = r[2]; bl[nf2*2+1][1] = r[3];
        }

        #pragma unroll
        for (int mf = 0; mf < 4; ++mf) {
            uint32_t off = sw32((a_row + (uint32_t)mf * 16u) * 32u + a_cb);
            uint32_t ah[4], al[4];
            ldsm4(ah, sAhi + off);
            ldsm4(al, sAlo + off);
            #pragma unroll
            for (int nf = 0; nf < 4; ++nf) {
                mma16816(acc[mf][nf], ah, bh[nf]);
                mma16816(acc[mf][nf], ah, bl[nf]);
                mma16816(acc[mf][nf], al, bh[nf]);
            }
        }
        // stage (kt+3)%4 == (kt-1)%4 was consumed last iter; top barrier makes reuse safe
        if (kt + 3 < nkt) load_stage((kt + 3) % NSTAGE, kt + 3);
    }

    const int gid = lane >> 2;
    const int tig = lane & 3;
    #pragma unroll
    for (int mf = 0; mf < 4; ++mf) {
        int row0 = mBase + wmB + mf * 16 + gid;
        #pragma unroll
        for (int nf = 0; nf < 4; ++nf) {
            int col = nBase + wnB + nf * 8 + tig * 2;
            if (col < Nreal) {
                float2 v0 = make_float2(acc[mf][nf][0], acc[mf][nf][1]);
                float2 v1 = make_float2(acc[mf][nf][2], acc[mf][nf][3]);
                *(float2*)(C + (size_t)row0 * Nreal + col) = v0;
                *(float2*)(C + (size_t)(row0 + 8) * Nreal + col) = v1;
            }
        }
    }
}

// ---------------- dt projection + softplus (64-row tiles, 256 blocks) --------
__global__ void __launch_bounds__(256)
dt_kernel(const float* __restrict__ W_dt, const float* __restrict__ dt_bias)
{
    __shared__ float s_r[64 * DT_RANK];    // 16KB
    const int t0 = blockIdx.x * 64;
    const int d  = blockIdx.y * 256 + threadIdx.x;

    #pragma unroll
    for (int k = 0; k < 16; ++k) {
        int idx = threadIdx.x + k * 256;
        int row = idx >> 6, col = idx & 63;
        s_r[idx] = g_zx[(size_t)(t0 + row) * D_PROJ + OFF_DT + col];
    }
    __syncthreads();

    float w[DT_RANK];
    #pragma unroll
    for (int k = 0; k < DT_RANK; ++k)
        w[k] = W_dt[(size_t)k * D_INNER + d];

    const float bias2 = 2.f * dt_bias[d];

    for (int tt = 0; tt < 64; ++tt) {
        const float4* rp = (const float4*)(s_r + tt * DT_RANK);
        float s = bias2;
        #pragma unroll
        for (int k4 = 0; k4 < DT_RANK / 4; ++k4) {
            float4 r4 = rp[k4];
            s = fmaf(r4.x, w[k4*4+0], s);
            s = fmaf(r4.y, w[k4*4+1], s);
            s = fmaf(r4.z, w[k4*4+2], s);
            s = fmaf(r4.w, w[k4*4+3], s);
        }
        float sp = (s > 20.f) ? s : log1pf(__expf(s));
        g_delta[(size_t)(t0 + tt) * D_INNER + d] = sp;
    }
}

// ---------------- causal depthwise conv (K=4) + bias + silu -----------------
__global__ void __launch_bounds__(256)
conv_kernel(const float* __restrict__ w, const float* __restrict__ b)
{
    int idx = blockIdx.x * blockDim.x + threadIdx.x;
    if (idx >= L_SEQ * D_XB) return;
    int t = idx >> 9, c = idx & (D_XB - 1);
    float acc = b[c];
    #pragma unroll
    for (int k = 0; k < KCONV; ++k) {
        int tt = t - (KCONV - 1) + k;
        if (tt >= 0)
            acc = fmaf(w[c * KCONV + k], g_zx[(size_t)tt * D_PROJ + OFF_X + c], acc);
    }
    g_xconv[idx] = acc / (1.f + __expf(-acc));
}

// ---------------- chunked selective scan -------------------------------------
__global__ void __launch_bounds__(256)
scan_phase_a(const float* __restrict__ A_log)
{
    const int g   = blockIdx.x;
    const int j   = blockIdx.y;
    const int tid = threadIdx.x;
    const int p   = tid >> 4;
    const int n   = tid & 15;
    const int gx  = g >> 2;
    const int d   = g * D_STATE + p;

    __shared__ float s_dv[CH * 16], s_xv[CH * 16], s_B[CH * 16];

    const int i0 = tid >> 4, l = tid & 15;
    const int tbase = j * CH;
    #pragma unroll
    for (int r = 0; r < CH; r += 16) {
        int t = tbase + i0 + r;
        s_dv[(i0 + r) * 16 + l] = g_delta[(size_t)t * D_INNER + g * 16 + l];
        s_xv[(i0 + r) * 16 + l] = g_xconv[(size_t)t * D_XB + gx * 16 + l];
        s_B [(i0 + r) * 16 + l] = g_zx[(size_t)t * D_PROJ + OFF_B + gx * 16 + l];
    }
    __syncthreads();

    const float A = -expf(A_log[d * D_STATE + n]);
    float h = 0.f, P = 1.f;
    #pragma unroll 8
    for (int i = 0; i < CH; ++i) {
        float dv = s_dv[i * 16 + p];
        float xv = s_xv[i * 16 + p];
        float Bv = s_B [i * 16 + n];
        float a  = __expf(dv * A);
        P *= a;
        h = fmaf(a, h, dv * xv * Bv);
    }
    int idx = (j * G_HEADS + g) * 256 + tid;
    g_P[idx] = P;
    g_E[idx] = h;
}

__global__ void __launch_bounds__(256)
scan_phase_b()
{
    const int g   = blockIdx.x;
    const int tid = threadIdx.x;
    float c = 0.f;
    #pragma unroll
    for (int j = 0; j < NCH; ++j) {
        int idx = (j * G_HEADS + g) * 256 + tid;
        float P = g_P[idx];
        float E = g_E[idx];
        g_Cin[idx] = c;
        c = fmaf(P, c, E);
    }
}

// Phase C: replay with carry, C-reduce, gate, write bf16 hi/lo for GEMM2
__global__ void __launch_bounds__(256)
scan_phase_c(const float* __restrict__ A_log, const float* __restrict__ Dp)
{
    const int g   = blockIdx.x;
    const int j   = blockIdx.y;
    const int tid = threadIdx.x;
    const int p   = tid >> 4;
    const int n   = tid & 15;
    const int gx  = g >> 2;
    const int d   = g * D_STATE + p;

    __shared__ float s_dv[CH * 16], s_xv[CH * 16], s_B[CH * 16],
                     s_C [CH * 16], s_z [CH * 16];

    const int i0 = tid >> 4, l = tid & 15;
    const int tbase = j * CH;
    #pragma unroll
    for (int r = 0; r < CH; r += 16) {
        int t = tbase + i0 + r;
        s_dv[(i0 + r) * 16 + l] = g_delta[(size_t)t * D_INNER + g * 16 + l];
        s_xv[(i0 + r) * 16 + l] = g_xconv[(size_t)t * D_XB + gx * 16 + l];
        s_B [(i0 + r) * 16 + l] = g_zx[(size_t)t * D_PROJ + OFF_B + gx * 16 + l];
        s_C [(i0 + r) * 16 + l] = g_zx[(size_t)t * D_PROJ + OFF_C + g * 16 + l];
        s_z [(i0 + r) * 16 + l] = g_zx[(size_t)t * D_PROJ + OFF_Z + g * 16 + l];
    }
    __syncthreads();

    const float A  = -expf(A_log[d * D_STATE + n]);
    const float Dv = Dp[d];
    float h = g_Cin[(j * G_HEADS + g) * 256 + tid];

    #pragma unroll 4
    for (int i = 0; i < CH; ++i) {
        float dv = s_dv[i * 16 + p];
        float xv = s_xv[i * 16 + p];
        float Bv = s_B [i * 16 + n];
        float Cv = s_C [i * 16 + n];

        float a = __expf(dv * A);
        h = fmaf(a, h, dv * xv * Bv);

        float part = h * Cv;
        part += __shfl_xor_sync(0xffffffffu, part, 8);
        part += __shfl_xor_sync(0xffffffffu, part, 4);
        part += __shfl_xor_sync(0xffffffffu, part, 2);
        part += __shfl_xor_sync(0xffffffffu, part, 1);

        if (n == 0) {
            float zv = s_z[i * 16 + p];
            float sz = zv / (1.f + __expf(-zv));
            float yv = (part + Dv * xv) * sz;
            size_t oi = (size_t)(tbase + i) * D_INNER + d;
            __nv_bfloat16 hb = __float2bfloat16_rn(yv);
            g_ahi[oi] = hb;
            g_alo[oi] = __float2bfloat16_rn(yv - __bfloat162float(hb));
        }
    }
}

// ---------------- launch ------------------------------------------------------
extern "C" void kernel_launch(void* const* d_in, const int* in_sizes, int n_in,
                              void* d_out, int out_size)
{
    const float* hidden  = (const float*)d_in[0];
    const float* W_in    = (const float*)d_in[1];
    const float* conv_w  = (const float*)d_in[2];
    const float* conv_b  = (const float*)d_in[3];
    const float* W_dt    = (const float*)d_in[4];
    const float* dt_bias = (const float*)d_in[5];
    const float* A_log   = (const float*)d_in[6];
    const float* Dp      = (const float*)d_in[7];
    const float* W_out   = (const float*)d_in[8];
    float*       out     = (float*)d_out;

    cudaFuncSetAttribute(gemm_tc_kernel,
                         cudaFuncAttributeMaxDynamicSharedMemorySize, GEMM_SMEM);

    float* zx;
    __nv_bfloat16 *ahi, *alo, *w1hi, *w1lo, *w2hi, *w2lo;
    cudaGetSymbolAddress((void**)&zx,   g_zx);
    cudaGetSymbolAddress((void**)&ahi,  g_ahi);
    cudaGetSymbolAddress((void**)&alo,  g_alo);
    cudaGetSymbolAddress((void**)&w1hi, g_w1hi);
    cudaGetSymbolAddress((void**)&w1lo, g_w1lo);
    cudaGetSymbolAddress((void**)&w2hi, g_w2hi);
    cudaGetSymbolAddress((void**)&w2lo, g_w2lo);

    // 1) split/transpose operands for GEMM1
    convert_hilo<<<(L_SEQ * D_MODEL) / 1024, 256>>>(hidden, ahi, alo, L_SEQ * D_MODEL);
    transpose_wt<<<dim3(NPAD1 / 32, D_MODEL / 32), 256>>>(W_in, w1hi, w1lo, D_MODEL, D_PROJ);

    // 2) zxbcdt = hidden @ W_in
    gemm_tc_kernel<<<dim3(NPAD1 / 128, L_SEQ / 128), 256, GEMM_SMEM>>>(
        ahi, alo, w1hi, w1lo, zx, D_PROJ, D_MODEL);

    // 3) delta + conv
    dt_kernel<<<dim3(L_SEQ / 64, D_INNER / 256), 256>>>(W_dt, dt_bias);
    conv_kernel<<<(L_SEQ * D_XB + 255) / 256, 256>>>(conv_w, conv_b);

    // 4) transpose W_out (independent of scan; scan overwrites g_ahi/g_alo)
    transpose_wt<<<dim3(D_MODEL / 32, D_INNER / 32), 256>>>(W_out, w2hi, w2lo, D_INNER, D_MODEL);

    // 5) chunked scan (phase C writes bf16 hi/lo yg directly into g_ahi/g_alo)
    scan_phase_a<<<dim3(G_HEADS, NCH), 256>>>(A_log);
    scan_phase_b<<<G_HEADS, 256>>>();
    scan_phase_c<<<dim3(G_HEADS, NCH), 256>>>(A_log, Dp);

    // 6) out = yg @ W_out
    gemm_tc_kernel<<<dim3(D_MODEL / 128, L_SEQ / 128), 256, GEMM_SMEM>>>(
        ahi, alo, w2hi, w2lo, out, D_MODEL, D_INNER);
}